// round 11
// baseline (speedup 1.0000x reference)
#include <cuda_runtime.h>
#include <mma.h>
using namespace nvcuda;

#define NN 50000
#define F  64        // in feats
#define KK 256       // F * K(=4) = GEMM K dim
#define OF 256       // out feats
#define EE 800000
#define SCAN_B 49    // ceil(NN/1024)
#define XTS 192      // g_Xt row stride (chunks 1..3 only; chunk 0 = signal)

// ---- scratch (static __device__ arrays; no allocation allowed) ----
// g_deg relies on zero-init at module load; scan3 re-zeroes it after use,
// so every call (and every graph replay) starts from a zeroed array.
__device__ int   g_deg[NN];                 // in-degree (int)
__device__ int   g_part[SCAN_B];            // per-block partial sums
__device__ float g_dsq[NN];                 // rsqrt(max(deg,1))
__device__ int   g_rowptr[NN + 1];          // CSR row pointers (in-edges by dst)
__device__ int   g_fill[NN];                // fill counters
__device__ int   g_col[EE];                 // CSR column (src node of each in-edge)
__device__ float g_Xt[(size_t)NN * XTS];    // packed [X1 | X2 | X3], 192 floats/node

// ---------------- degree ----------------
__global__ void deg_kernel(const int* __restrict__ dst, int E) {
    int e = blockIdx.x * blockDim.x + threadIdx.x;
    if (e < E) atomicAdd(&g_deg[dst[e]], 1);
}

// ---- 2-phase scan: block sums -> (inline partial scan) block scan + outputs ----
__global__ __launch_bounds__(1024)
void scan1_kernel() {
    __shared__ int red[32];
    int i = blockIdx.x * 1024 + threadIdx.x;
    int d = (i < NN) ? g_deg[i] : 0;
    for (int o = 16; o > 0; o >>= 1) d += __shfl_down_sync(0xffffffff, d, o);
    if ((threadIdx.x & 31) == 0) red[threadIdx.x >> 5] = d;
    __syncthreads();
    if (threadIdx.x < 32) {
        int v = red[threadIdx.x];
        for (int o = 16; o > 0; o >>= 1) v += __shfl_down_sync(0xffffffff, v, o);
        if (threadIdx.x == 0) g_part[blockIdx.x] = v;
    }
}

__global__ __launch_bounds__(1024)
void scan3_kernel() {
    __shared__ int sh[1024];
    __shared__ int base_s;
    int t = threadIdx.x;
    int bid = blockIdx.x;
    int i = bid * 1024 + t;

    if (t == 0) {
        int s = 0;
        for (int k = 0; k < bid; k++) s += g_part[k];
        base_s = s;
        if (bid == SCAN_B - 1) {           // this block also computes the total
            int tot = s;
            for (int k = bid; k < SCAN_B; k++) tot += g_part[k];
            g_rowptr[NN] = tot;
        }
    }

    int d = (i < NN) ? g_deg[i] : 0;
    sh[t] = d;
    __syncthreads();
    for (int off = 1; off < 1024; off <<= 1) {
        int u = (t >= off) ? sh[t - off] : 0;
        __syncthreads();
        sh[t] += u;
        __syncthreads();
    }
    if (i < NN) {
        g_rowptr[i] = base_s + sh[t] - d;   // exclusive prefix
        g_fill[i] = 0;
        g_dsq[i] = rsqrtf(fmaxf((float)d, 1.0f));
        g_deg[i] = 0;                       // re-zero for next call / replay
    }
}

__global__ void fill_kernel(const int* __restrict__ src,
                            const int* __restrict__ dst, int E) {
    int e = blockIdx.x * blockDim.x + threadIdx.x;
    if (e >= E) return;
    int d = dst[e];
    int pos = g_rowptr[d] + atomicAdd(&g_fill[d], 1);
    g_col[pos] = src[e];
}

// ---------------- fused Chebyshev step: gather + combine, no atomics ----------------
// warp per node, 4-edge unroll.
// Operand encoding: off < 0 -> signal (stride F); off >= 0 -> g_Xt + off (stride XTS).
// Pointers are resolved in DEVICE code (g_Xt is a __device__ symbol).
__device__ __forceinline__ const float* op_ptr(const float* sig, int off, int& stride) {
    if (off < 0) { stride = F; return sig; }
    stride = XTS; return g_Xt + off;
}

__global__ __launch_bounds__(256)
void cheb_step_kernel(const float* __restrict__ lam, const float* __restrict__ sig,
                      int in_off, int p1_off, int p2_off, int out_off, int step) {
    int gtid = blockIdx.x * blockDim.x + threadIdx.x;
    int v = gtid >> 5;
    int lane = gtid & 31;
    if (v >= NN) return;

    int strin, strp1, strp2;
    const float* xin = op_ptr(sig, in_off, strin);
    const float* xp1 = op_ptr(sig, p1_off, strp1);
    const float* xp2 = op_ptr(sig, p2_off, strp2);
    float* xout = g_Xt + out_off;           // outputs always land in g_Xt

    int p   = g_rowptr[v];
    int end = g_rowptr[v + 1];
    float ax = 0.0f, ay = 0.0f;

    const float* Xin = xin + lane * 2;
    for (; p + 3 < end; p += 4) {
        int s0 = g_col[p];
        int s1 = g_col[p + 1];
        int s2 = g_col[p + 2];
        int s3 = g_col[p + 3];
        float d0 = g_dsq[s0];
        float d1 = g_dsq[s1];
        float d2 = g_dsq[s2];
        float d3 = g_dsq[s3];
        float2 x0 = *(const float2*)(Xin + (size_t)s0 * strin);
        float2 x1 = *(const float2*)(Xin + (size_t)s1 * strin);
        float2 x2 = *(const float2*)(Xin + (size_t)s2 * strin);
        float2 x3 = *(const float2*)(Xin + (size_t)s3 * strin);
        ax += d0 * x0.x + d1 * x1.x + d2 * x2.x + d3 * x3.x;
        ay += d0 * x0.y + d1 * x1.y + d2 * x2.y + d3 * x3.y;
    }
    for (; p < end; p++) {
        int s0 = g_col[p];
        float d0 = g_dsq[s0];
        float2 x0 = *(const float2*)(Xin + (size_t)s0 * strin);
        ax += d0 * x0.x;
        ay += d0 * x0.y;
    }

    float dsv = g_dsq[v];
    float r = 2.0f / lam[0];
    float Lx = ax * dsv, Ly = ay * dsv;

    float2 p1 = *(const float2*)(xp1 + (size_t)v * strp1 + lane * 2);
    float2 out;
    if (step == 1) {
        out.x = -r * Lx + (r - 1.0f) * p1.x;
        out.y = -r * Ly + (r - 1.0f) * p1.y;
    } else {
        float2 p2 = *(const float2*)(xp2 + (size_t)v * strp2 + lane * 2);
        out.x = -2.0f * r * Lx + 2.0f * (r - 1.0f) * p1.x - p2.x;
        out.y = -2.0f * r * Ly + 2.0f * (r - 1.0f) * p1.y - p2.y;
    }
    *(float2*)(xout + (size_t)v * XTS + lane * 2) = out;
}

// ---------------- 2-stage pipelined tf32 tensor-core GEMM + bias + ReLU ----------------
// A row gr: k<64 -> signal[gr*64+k] ; k>=64 -> g_Xt[gr*192 + (k-64)]
#define GBM 128
#define GBN 128
#define GBK 16
#define AROW 28
#define BROW 140
#define ASTG (GBM * AROW)          // 3584
#define STG  (ASTG + GBK * BROW)   // 5824 floats / stage

__device__ __forceinline__ void cp16(float* dstp, const float* src, int sz) {
    unsigned saddr = (unsigned)__cvta_generic_to_shared(dstp);
    asm volatile("cp.async.ca.shared.global [%0], [%1], 16, %2;"
                 :: "r"(saddr), "l"(src), "r"(sz));
}

__global__ __launch_bounds__(256)
void gemm_tf32(const float* __restrict__ signal,
               const float* __restrict__ W, const float* __restrict__ bias,
               float* __restrict__ C, int M) {
    __shared__ float sm[2 * STG];   // 46.6 KB

    int bx = blockIdx.x, by = blockIdx.y;
    int tid = threadIdx.x;
    int warp = tid >> 5, lane = tid & 31;
    int wm = warp >> 2;
    int wn = warp & 3;

    wmma::fragment<wmma::accumulator, 16, 16, 8, float> acc[4][2];
#pragma unroll
    for (int i = 0; i < 4; i++)
#pragma unroll
        for (int j = 0; j < 2; j++) wmma::fill_fragment(acc[i][j], 0.0f);

    const int NT = KK / GBK;   // 16

    auto load_stage = [&](int t, int stg) {
        float* s = sm + stg * STG;
        int k0 = t * GBK;
#pragma unroll
        for (int it = 0; it < 2; it++) {
            int idx = tid + it * 256;
            int row = idx >> 2, c4 = idx & 3;
            int gr = by * GBM + row;
            int grc = (gr < M) ? gr : (M - 1);
            const float* srcp;
            if (k0 < F)
                srcp = signal + (size_t)grc * F + k0 + c4 * 4;
            else
                srcp = g_Xt + (size_t)grc * XTS + (k0 - F) + c4 * 4;
            cp16(s + row * AROW + c4 * 4, srcp, (gr < M) ? 16 : 0);
        }
#pragma unroll
        for (int it = 0; it < 2; it++) {
            int idx = tid + it * 256;
            int row = idx >> 5, c4 = idx & 31;
            const float* srcp = W + (size_t)(k0 + row) * OF + bx * GBN + c4 * 4;
            cp16(s + ASTG + row * BROW + c4 * 4, srcp, 16);
        }
        asm volatile("cp.async.commit_group;");
    };

    load_stage(0, 0);

    for (int t = 0; t < NT; t++) {
        if (t + 1 < NT) {
            load_stage(t + 1, (t + 1) & 1);
            asm volatile("cp.async.wait_group 1;");
        } else {
            asm volatile("cp.async.wait_group 0;");
        }
        __syncthreads();

        const float* s = sm + (t & 1) * STG;
#pragma unroll
        for (int kk = 0; kk < GBK; kk += 8) {
            wmma::fragment<wmma::matrix_a, 16, 16, 8, wmma::precision::tf32, wmma::row_major> af[4];
            wmma::fragment<wmma::matrix_b, 16, 16, 8, wmma::precision::tf32, wmma::row_major> bf[2];
#pragma unroll
            for (int i = 0; i < 4; i++) {
                wmma::load_matrix_sync(af[i], s + (wm * 64 + i * 16) * AROW + kk, AROW);
#pragma unroll
                for (int e = 0; e < af[i].num_elements; e++)
                    af[i].x[e] = wmma::__float_to_tf32(af[i].x[e]);
            }
#pragma unroll
            for (int j = 0; j < 2; j++) {
                wmma::load_matrix_sync(bf[j], s + ASTG + kk * BROW + wn * 32 + j * 16, BROW);
#pragma unroll
                for (int e = 0; e < bf[j].num_elements; e++)
                    bf[j].x[e] = wmma::__float_to_tf32(bf[j].x[e]);
            }
#pragma unroll
            for (int i = 0; i < 4; i++)
#pragma unroll
                for (int j = 0; j < 2; j++)
                    wmma::mma_sync(acc[i][j], af[i], bf[j], acc[i][j]);
        }
        __syncthreads();
    }

    float* Cw = sm + warp * 256;
#pragma unroll
    for (int i = 0; i < 4; i++) {
#pragma unroll
        for (int j = 0; j < 2; j++) {
            wmma::store_matrix_sync(Cw, acc[i][j], 16, wmma::mem_row_major);
            __syncwarp();
            int r0 = by * GBM + wm * 64 + i * 16;
            int c0 = bx * GBN + wn * 32 + j * 16;
            int lr = lane >> 1;
            int lc = (lane & 1) * 8;
            int row = r0 + lr;
            if (row < M) {
#pragma unroll
                for (int c = 0; c < 8; c += 4) {
                    int col = c0 + lc + c;
                    float4 o;
                    o.x = fmaxf(Cw[lr * 16 + lc + c + 0] + bias[col + 0], 0.0f);
                    o.y = fmaxf(Cw[lr * 16 + lc + c + 1] + bias[col + 1], 0.0f);
                    o.z = fmaxf(Cw[lr * 16 + lc + c + 2] + bias[col + 2], 0.0f);
                    o.w = fmaxf(Cw[lr * 16 + lc + c + 3] + bias[col + 3], 0.0f);
                    *(float4*)(C + (size_t)row * OF + col) = o;
                }
            }
            __syncwarp();
        }
    }
}

// ---------------- launch ----------------
extern "C" void kernel_launch(void* const* d_in, const int* in_sizes, int n_in,
                              void* d_out, int out_size) {
    const float* signal = (const float*)d_in[0];
    const int*   src    = (const int*)d_in[1];
    const int*   dst    = (const int*)d_in[2];
    const float* lam    = (const float*)d_in[3];
    const float* W      = (const float*)d_in[4];
    const float* b      = (const float*)d_in[5];
    float* out = (float*)d_out;

    const int E = in_sizes[1];
    const int EB = (E + 255) / 256;

    // degrees + CSR (g_deg arrives zeroed; scan3 re-zeroes it for the next call)
    deg_kernel<<<EB, 256>>>(dst, E);
    scan1_kernel<<<SCAN_B, 1024>>>();
    scan3_kernel<<<SCAN_B, 1024>>>();
    fill_kernel<<<EB, 256>>>(src, dst, E);

    // Chebyshev passes (warp per node; X0 = signal read in place).
    // Offsets: -1 = signal; 0/64/128 = X1/X2/X3 inside g_Xt (resolved device-side).
    const int CB = (NN * 32 + 255) / 256;
    cheb_step_kernel<<<CB, 256>>>(lam, signal, /*in*/-1, /*p1*/-1, /*p2*/-1, /*out*/0,   1);
    cheb_step_kernel<<<CB, 256>>>(lam, signal, /*in*/0,  /*p1*/0,  /*p2*/-1, /*out*/64,  2);
    cheb_step_kernel<<<CB, 256>>>(lam, signal, /*in*/64, /*p1*/64, /*p2*/0,  /*out*/128, 2);

    // out = relu([signal | X1 | X2 | X3] @ W + b) -- 2-stage pipelined tf32
    dim3 grid(OF / GBN, (NN + GBM - 1) / GBM);
    gemm_tf32<<<grid, 256>>>(signal, W, b, out, NN);
}

// round 13
// speedup vs baseline: 1.0600x; 1.0600x over previous
#include <cuda_runtime.h>
#include <mma.h>
using namespace nvcuda;

#define NN 50000
#define F  64        // in feats
#define KK 256       // F * K(=4) = GEMM K dim
#define OF 256       // out feats
#define EE 800000
#define SCAN_B 49    // ceil(NN/1024)

// ---- scratch (static __device__ arrays; no allocation allowed) ----
// g_deg relies on zero-init at module load; scan3 re-zeroes it after use,
// so every call (and every graph replay) starts from a zeroed array.
__device__ int   g_deg[NN];                 // in-degree (int)
__device__ int   g_part[SCAN_B];            // per-block partial sums
__device__ float g_dsq[NN];                 // rsqrt(max(deg,1))
__device__ int   g_rowptr[NN + 1];          // CSR row pointers (in-edges by dst)
__device__ int   g_fill[NN];                // fill counters
__device__ int   g_col[EE];                 // CSR column (src node of each in-edge)
__device__ float g_Xt[(size_t)NN * KK];     // packed [X0 | X1 | X2 | X3]

// ---------------- degree (2 edges/thread for MLP) ----------------
__global__ void deg_kernel(const int* __restrict__ dst, int E) {
    int t = blockIdx.x * blockDim.x + threadIdx.x;
    int e0 = t * 2;
    if (e0 + 1 < E) {
        int d0 = dst[e0];
        int d1 = dst[e0 + 1];
        atomicAdd(&g_deg[d0], 1);
        atomicAdd(&g_deg[d1], 1);
    } else if (e0 < E) {
        atomicAdd(&g_deg[dst[e0]], 1);
    }
}

// ---- 2-phase scan: block sums -> (inline partial scan) block scan + outputs ----
__global__ __launch_bounds__(1024)
void scan1_kernel() {
    __shared__ int red[32];
    int i = blockIdx.x * 1024 + threadIdx.x;
    int d = (i < NN) ? g_deg[i] : 0;
    for (int o = 16; o > 0; o >>= 1) d += __shfl_down_sync(0xffffffff, d, o);
    if ((threadIdx.x & 31) == 0) red[threadIdx.x >> 5] = d;
    __syncthreads();
    if (threadIdx.x < 32) {
        int v = red[threadIdx.x];
        for (int o = 16; o > 0; o >>= 1) v += __shfl_down_sync(0xffffffff, v, o);
        if (threadIdx.x == 0) g_part[blockIdx.x] = v;
    }
}

__global__ __launch_bounds__(1024)
void scan3_kernel() {
    __shared__ int sh[1024];
    __shared__ int base_s;
    int t = threadIdx.x;
    int bid = blockIdx.x;
    int i = bid * 1024 + t;

    if (t == 0) {
        int s = 0;
        for (int k = 0; k < bid; k++) s += g_part[k];
        base_s = s;
        if (bid == SCAN_B - 1) {           // this block also computes the total
            int tot = s;
            for (int k = bid; k < SCAN_B; k++) tot += g_part[k];
            g_rowptr[NN] = tot;
        }
    }

    int d = (i < NN) ? g_deg[i] : 0;
    sh[t] = d;
    __syncthreads();
    for (int off = 1; off < 1024; off <<= 1) {
        int u = (t >= off) ? sh[t - off] : 0;
        __syncthreads();
        sh[t] += u;
        __syncthreads();
    }
    if (i < NN) {
        g_rowptr[i] = base_s + sh[t] - d;   // exclusive prefix
        g_fill[i] = 0;
        g_dsq[i] = rsqrtf(fmaxf((float)d, 1.0f));
        g_deg[i] = 0;                       // re-zero for next call / replay
    }
}

// ---------------- CSR fill (2 edges/thread for MLP) ----------------
__global__ void fill_kernel(const int* __restrict__ src,
                            const int* __restrict__ dst, int E) {
    int t = blockIdx.x * blockDim.x + threadIdx.x;
    int e0 = t * 2;
    if (e0 + 1 < E) {
        int d0 = dst[e0];
        int d1 = dst[e0 + 1];
        int s0 = src[e0];
        int s1 = src[e0 + 1];
        int p0 = g_rowptr[d0] + atomicAdd(&g_fill[d0], 1);
        int p1 = g_rowptr[d1] + atomicAdd(&g_fill[d1], 1);
        g_col[p0] = s0;
        g_col[p1] = s1;
    } else if (e0 < E) {
        int d0 = dst[e0];
        int p0 = g_rowptr[d0] + atomicAdd(&g_fill[d0], 1);
        g_col[p0] = src[e0];
    }
}

// ---------------- init: X0 into Xt chunk0 ----------------
__global__ void init_kernel(const float* __restrict__ sig) {
    int i = blockIdx.x * blockDim.x + threadIdx.x;
    if (i >= NN * (F / 4)) return;
    int row = i >> 4;
    int c4  = i & 15;
    float4 v = ((const float4*)sig)[i];
    ((float4*)(g_Xt + (size_t)row * KK))[c4] = v;
}

// ---------------- fused Chebyshev step: gather + combine, no atomics ----------------
// warp per node, 4-edge unroll, compile-time KK stride (R9-proven form)
__global__ __launch_bounds__(256)
void cheb_step_kernel(const float* __restrict__ lam,
                      int in_off, int out_off, int p1_off, int p2_off, int step) {
    int gtid = blockIdx.x * blockDim.x + threadIdx.x;
    int v = gtid >> 5;
    int lane = gtid & 31;
    if (v >= NN) return;

    int p   = g_rowptr[v];
    int end = g_rowptr[v + 1];
    float ax = 0.0f, ay = 0.0f;

    const float* Xin = g_Xt + in_off + lane * 2;
    for (; p + 3 < end; p += 4) {
        int s0 = g_col[p];
        int s1 = g_col[p + 1];
        int s2 = g_col[p + 2];
        int s3 = g_col[p + 3];
        float d0 = g_dsq[s0];
        float d1 = g_dsq[s1];
        float d2 = g_dsq[s2];
        float d3 = g_dsq[s3];
        float2 x0 = *(const float2*)(Xin + (size_t)s0 * KK);
        float2 x1 = *(const float2*)(Xin + (size_t)s1 * KK);
        float2 x2 = *(const float2*)(Xin + (size_t)s2 * KK);
        float2 x3 = *(const float2*)(Xin + (size_t)s3 * KK);
        ax += d0 * x0.x + d1 * x1.x + d2 * x2.x + d3 * x3.x;
        ay += d0 * x0.y + d1 * x1.y + d2 * x2.y + d3 * x3.y;
    }
    for (; p < end; p++) {
        int s0 = g_col[p];
        float d0 = g_dsq[s0];
        float2 x0 = *(const float2*)(Xin + (size_t)s0 * KK);
        ax += d0 * x0.x;
        ay += d0 * x0.y;
    }

    float dsv = g_dsq[v];
    float r = 2.0f / lam[0];
    float Lx = ax * dsv, Ly = ay * dsv;

    const float* base = g_Xt + (size_t)v * KK + lane * 2;
    float2 p1 = *(const float2*)(base + p1_off);
    float2 out;
    if (step == 1) {
        out.x = -r * Lx + (r - 1.0f) * p1.x;
        out.y = -r * Ly + (r - 1.0f) * p1.y;
    } else {
        float2 p2 = *(const float2*)(base + p2_off);
        out.x = -2.0f * r * Lx + 2.0f * (r - 1.0f) * p1.x - p2.x;
        out.y = -2.0f * r * Ly + 2.0f * (r - 1.0f) * p1.y - p2.y;
    }
    *(float2*)(g_Xt + (size_t)v * KK + out_off + lane * 2) = out;
}

// ---------------- 2-stage pipelined tf32 tensor-core GEMM + bias + ReLU ----------------
#define GBM 128
#define GBN 128
#define GBK 16
#define AROW 28
#define BROW 140
#define ASTG (GBM * AROW)          // 3584
#define STG  (ASTG + GBK * BROW)   // 5824 floats / stage

__device__ __forceinline__ void cp16(float* dstp, const float* src, int sz) {
    unsigned saddr = (unsigned)__cvta_generic_to_shared(dstp);
    asm volatile("cp.async.ca.shared.global [%0], [%1], 16, %2;"
                 :: "r"(saddr), "l"(src), "r"(sz));
}

__global__ __launch_bounds__(256)
void gemm_tf32(const float* __restrict__ W, const float* __restrict__ bias,
               float* __restrict__ C, int M) {
    __shared__ float sm[2 * STG];   // 46.6 KB

    int bx = blockIdx.x, by = blockIdx.y;
    int tid = threadIdx.x;
    int warp = tid >> 5, lane = tid & 31;
    int wm = warp >> 2;
    int wn = warp & 3;

    wmma::fragment<wmma::accumulator, 16, 16, 8, float> acc[4][2];
#pragma unroll
    for (int i = 0; i < 4; i++)
#pragma unroll
        for (int j = 0; j < 2; j++) wmma::fill_fragment(acc[i][j], 0.0f);

    const int NT = KK / GBK;   // 16

    auto load_stage = [&](int t, int stg) {
        float* s = sm + stg * STG;
        int k0 = t * GBK;
#pragma unroll
        for (int it = 0; it < 2; it++) {
            int idx = tid + it * 256;
            int row = idx >> 2, c4 = idx & 3;
            int gr = by * GBM + row;
            int grc = (gr < M) ? gr : (M - 1);
            const float* srcp = g_Xt + (size_t)grc * KK + k0 + c4 * 4;
            cp16(s + row * AROW + c4 * 4, srcp, (gr < M) ? 16 : 0);
        }
#pragma unroll
        for (int it = 0; it < 2; it++) {
            int idx = tid + it * 256;
            int row = idx >> 5, c4 = idx & 31;
            const float* srcp = W + (size_t)(k0 + row) * OF + bx * GBN + c4 * 4;
            cp16(s + ASTG + row * BROW + c4 * 4, srcp, 16);
        }
        asm volatile("cp.async.commit_group;");
    };

    load_stage(0, 0);

    for (int t = 0; t < NT; t++) {
        if (t + 1 < NT) {
            load_stage(t + 1, (t + 1) & 1);
            asm volatile("cp.async.wait_group 1;");
        } else {
            asm volatile("cp.async.wait_group 0;");
        }
        __syncthreads();

        const float* s = sm + (t & 1) * STG;
#pragma unroll
        for (int kk = 0; kk < GBK; kk += 8) {
            wmma::fragment<wmma::matrix_a, 16, 16, 8, wmma::precision::tf32, wmma::row_major> af[4];
            wmma::fragment<wmma::matrix_b, 16, 16, 8, wmma::precision::tf32, wmma::row_major> bf[2];
#pragma unroll
            for (int i = 0; i < 4; i++) {
                wmma::load_matrix_sync(af[i], s + (wm * 64 + i * 16) * AROW + kk, AROW);
#pragma unroll
                for (int e = 0; e < af[i].num_elements; e++)
                    af[i].x[e] = wmma::__float_to_tf32(af[i].x[e]);
            }
#pragma unroll
            for (int j = 0; j < 2; j++) {
                wmma::load_matrix_sync(bf[j], s + ASTG + kk * BROW + wn * 32 + j * 16, BROW);
#pragma unroll
                for (int e = 0; e < bf[j].num_elements; e++)
                    bf[j].x[e] = wmma::__float_to_tf32(bf[j].x[e]);
            }
#pragma unroll
            for (int i = 0; i < 4; i++)
#pragma unroll
                for (int j = 0; j < 2; j++)
                    wmma::mma_sync(acc[i][j], af[i], bf[j], acc[i][j]);
        }
        __syncthreads();
    }

    float* Cw = sm + warp * 256;
#pragma unroll
    for (int i = 0; i < 4; i++) {
#pragma unroll
        for (int j = 0; j < 2; j++) {
            wmma::store_matrix_sync(Cw, acc[i][j], 16, wmma::mem_row_major);
            __syncwarp();
            int r0 = by * GBM + wm * 64 + i * 16;
            int c0 = bx * GBN + wn * 32 + j * 16;
            int lr = lane >> 1;
            int lc = (lane & 1) * 8;
            int row = r0 + lr;
            if (row < M) {
#pragma unroll
                for (int c = 0; c < 8; c += 4) {
                    int col = c0 + lc + c;
                    float4 o;
                    o.x = fmaxf(Cw[lr * 16 + lc + c + 0] + bias[col + 0], 0.0f);
                    o.y = fmaxf(Cw[lr * 16 + lc + c + 1] + bias[col + 1], 0.0f);
                    o.z = fmaxf(Cw[lr * 16 + lc + c + 2] + bias[col + 2], 0.0f);
                    o.w = fmaxf(Cw[lr * 16 + lc + c + 3] + bias[col + 3], 0.0f);
                    *(float4*)(C + (size_t)row * OF + col) = o;
                }
            }
            __syncwarp();
        }
    }
}

// ---------------- launch ----------------
extern "C" void kernel_launch(void* const* d_in, const int* in_sizes, int n_in,
                              void* d_out, int out_size) {
    const float* signal = (const float*)d_in[0];
    const int*   src    = (const int*)d_in[1];
    const int*   dst    = (const int*)d_in[2];
    const float* lam    = (const float*)d_in[3];
    const float* W      = (const float*)d_in[4];
    const float* b      = (const float*)d_in[5];
    float* out = (float*)d_out;

    const int E = in_sizes[1];
    const int EB2 = ((E + 1) / 2 + 255) / 256;   // 2 edges per thread

    // degrees + CSR (g_deg arrives zeroed; scan3 re-zeroes it for the next call)
    deg_kernel<<<EB2, 256>>>(dst, E);
    scan1_kernel<<<SCAN_B, 1024>>>();
    scan3_kernel<<<SCAN_B, 1024>>>();
    fill_kernel<<<EB2, 256>>>(src, dst, E);

    // X0
    init_kernel<<<(NN * 16 + 255) / 256, 256>>>(signal);

    // Chebyshev passes (warp per node, fused gather+combine, 4-edge unroll)
    const int CB = (NN * 32 + 255) / 256;
    cheb_step_kernel<<<CB, 256>>>(lam, /*in*/0,   /*out*/64,  /*p1*/0,   /*p2*/0,  1);
    cheb_step_kernel<<<CB, 256>>>(lam, /*in*/64,  /*out*/128, /*p1*/64,  /*p2*/0,  2);
    cheb_step_kernel<<<CB, 256>>>(lam, /*in*/128, /*out*/192, /*p1*/128, /*p2*/64, 2);

    // out = relu(Xt @ W + b)  -- 2-stage pipelined tf32 tensor cores
    dim3 grid(OF / GBN, (NN + GBM - 1) / GBM);
    gemm_tf32<<<grid, 256>>>(W, b, out, NN);
}

// round 14
// speedup vs baseline: 1.0786x; 1.0176x over previous
#include <cuda_runtime.h>
#include <mma.h>
using namespace nvcuda;

#define NN 50000
#define F  64        // in feats
#define KK 256       // F * K(=4) = GEMM K dim
#define OF 256       // out feats
#define EE 800000
#define SCAN_B 49    // ceil(NN/1024)

// ---- scratch (static __device__ arrays; no allocation allowed) ----
// g_deg relies on zero-init at module load; scan3 re-zeroes it after use,
// so every call (and every graph replay) starts from a zeroed array.
__device__ int   g_deg[NN];                 // in-degree (int)
__device__ int   g_part[SCAN_B];            // per-block partial sums
__device__ float g_dsq[NN];                 // rsqrt(max(deg,1))
__device__ int   g_rowptr[NN + 1];          // CSR row pointers (in-edges by dst)
__device__ int   g_fill[NN];                // fill counters
__device__ int   g_col[EE];                 // CSR column (src node of each in-edge)
__device__ float g_Xt[(size_t)NN * KK];     // packed [X0 | X1 | X2 | X3]

// ---------------- degree (2 edges/thread) ----------------
__global__ void deg_kernel(const int* __restrict__ dst, int E) {
    int t = blockIdx.x * blockDim.x + threadIdx.x;
    int e0 = t * 2;
    if (e0 + 1 < E) {
        int d0 = dst[e0];
        int d1 = dst[e0 + 1];
        atomicAdd(&g_deg[d0], 1);
        atomicAdd(&g_deg[d1], 1);
    } else if (e0 < E) {
        atomicAdd(&g_deg[dst[e0]], 1);
    }
}

// ---- 2-phase scan: block sums -> (inline partial scan) block scan + outputs ----
__global__ __launch_bounds__(1024)
void scan1_kernel() {
    __shared__ int red[32];
    int i = blockIdx.x * 1024 + threadIdx.x;
    int d = (i < NN) ? g_deg[i] : 0;
    for (int o = 16; o > 0; o >>= 1) d += __shfl_down_sync(0xffffffff, d, o);
    if ((threadIdx.x & 31) == 0) red[threadIdx.x >> 5] = d;
    __syncthreads();
    if (threadIdx.x < 32) {
        int v = red[threadIdx.x];
        for (int o = 16; o > 0; o >>= 1) v += __shfl_down_sync(0xffffffff, v, o);
        if (threadIdx.x == 0) g_part[blockIdx.x] = v;
    }
}

__global__ __launch_bounds__(1024)
void scan3_kernel() {
    __shared__ int sh[1024];
    __shared__ int base_s;
    int t = threadIdx.x;
    int bid = blockIdx.x;
    int i = bid * 1024 + t;

    if (t == 0) {
        int s = 0;
        for (int k = 0; k < bid; k++) s += g_part[k];
        base_s = s;
        if (bid == SCAN_B - 1) {           // this block also computes the total
            int tot = s;
            for (int k = bid; k < SCAN_B; k++) tot += g_part[k];
            g_rowptr[NN] = tot;
        }
    }

    int d = (i < NN) ? g_deg[i] : 0;
    sh[t] = d;
    __syncthreads();
    for (int off = 1; off < 1024; off <<= 1) {
        int u = (t >= off) ? sh[t - off] : 0;
        __syncthreads();
        sh[t] += u;
        __syncthreads();
    }
    if (i < NN) {
        g_rowptr[i] = base_s + sh[t] - d;   // exclusive prefix
        g_fill[i] = 0;
        g_dsq[i] = rsqrtf(fmaxf((float)d, 1.0f));
        g_deg[i] = 0;                       // re-zero for next call / replay
    }
}

// ---------------- CSR fill (2 edges/thread) ----------------
__global__ void fill_kernel(const int* __restrict__ src,
                            const int* __restrict__ dst, int E) {
    int t = blockIdx.x * blockDim.x + threadIdx.x;
    int e0 = t * 2;
    if (e0 + 1 < E) {
        int d0 = dst[e0];
        int d1 = dst[e0 + 1];
        int s0 = src[e0];
        int s1 = src[e0 + 1];
        int p0 = g_rowptr[d0] + atomicAdd(&g_fill[d0], 1);
        int p1 = g_rowptr[d1] + atomicAdd(&g_fill[d1], 1);
        g_col[p0] = s0;
        g_col[p1] = s1;
    } else if (e0 < E) {
        int d0 = dst[e0];
        int p0 = g_rowptr[d0] + atomicAdd(&g_fill[d0], 1);
        g_col[p0] = src[e0];
    }
}

// ---------------- cheb pass 1 (fused init): reads signal only ----------------
// warp per node v:
//   agg = sum dsq[src] * signal[src]          (compile-time stride F)
//   X1  = -r*dsq[v]*agg + (r-1)*signal[v]
//   also copies signal[v] row into Xt chunk 0.
__global__ __launch_bounds__(256)
void cheb_step1_kernel(const float* __restrict__ lam,
                       const float* __restrict__ sig) {
    int gtid = blockIdx.x * blockDim.x + threadIdx.x;
    int v = gtid >> 5;
    int lane = gtid & 31;
    if (v >= NN) return;

    int p   = g_rowptr[v];
    int end = g_rowptr[v + 1];
    float ax = 0.0f, ay = 0.0f;

    const float* Sin = sig + lane * 2;
    for (; p + 3 < end; p += 4) {
        int s0 = g_col[p];
        int s1 = g_col[p + 1];
        int s2 = g_col[p + 2];
        int s3 = g_col[p + 3];
        float d0 = g_dsq[s0];
        float d1 = g_dsq[s1];
        float d2 = g_dsq[s2];
        float d3 = g_dsq[s3];
        float2 x0 = *(const float2*)(Sin + (size_t)s0 * F);
        float2 x1 = *(const float2*)(Sin + (size_t)s1 * F);
        float2 x2 = *(const float2*)(Sin + (size_t)s2 * F);
        float2 x3 = *(const float2*)(Sin + (size_t)s3 * F);
        ax += d0 * x0.x + d1 * x1.x + d2 * x2.x + d3 * x3.x;
        ay += d0 * x0.y + d1 * x1.y + d2 * x2.y + d3 * x3.y;
    }
    for (; p < end; p++) {
        int s0 = g_col[p];
        float d0 = g_dsq[s0];
        float2 x0 = *(const float2*)(Sin + (size_t)s0 * F);
        ax += d0 * x0.x;
        ay += d0 * x0.y;
    }

    float dsv = g_dsq[v];
    float r = 2.0f / lam[0];
    float Lx = ax * dsv, Ly = ay * dsv;

    float2 x0v = *(const float2*)(sig + (size_t)v * F + lane * 2);
    float2 out;
    out.x = -r * Lx + (r - 1.0f) * x0v.x;
    out.y = -r * Ly + (r - 1.0f) * x0v.y;

    float* row = g_Xt + (size_t)v * KK + lane * 2;
    *(float2*)(row) = x0v;            // X0 copy (chunk 0)
    *(float2*)(row + 64) = out;       // X1      (chunk 1)
}

// ---------------- cheb passes 2..3 (R13-proven form, g_Xt only) ----------------
__global__ __launch_bounds__(256)
void cheb_step_kernel(const float* __restrict__ lam,
                      int in_off, int out_off, int p1_off, int p2_off) {
    int gtid = blockIdx.x * blockDim.x + threadIdx.x;
    int v = gtid >> 5;
    int lane = gtid & 31;
    if (v >= NN) return;

    int p   = g_rowptr[v];
    int end = g_rowptr[v + 1];
    float ax = 0.0f, ay = 0.0f;

    const float* Xin = g_Xt + in_off + lane * 2;
    for (; p + 3 < end; p += 4) {
        int s0 = g_col[p];
        int s1 = g_col[p + 1];
        int s2 = g_col[p + 2];
        int s3 = g_col[p + 3];
        float d0 = g_dsq[s0];
        float d1 = g_dsq[s1];
        float d2 = g_dsq[s2];
        float d3 = g_dsq[s3];
        float2 x0 = *(const float2*)(Xin + (size_t)s0 * KK);
        float2 x1 = *(const float2*)(Xin + (size_t)s1 * KK);
        float2 x2 = *(const float2*)(Xin + (size_t)s2 * KK);
        float2 x3 = *(const float2*)(Xin + (size_t)s3 * KK);
        ax += d0 * x0.x + d1 * x1.x + d2 * x2.x + d3 * x3.x;
        ay += d0 * x0.y + d1 * x1.y + d2 * x2.y + d3 * x3.y;
    }
    for (; p < end; p++) {
        int s0 = g_col[p];
        float d0 = g_dsq[s0];
        float2 x0 = *(const float2*)(Xin + (size_t)s0 * KK);
        ax += d0 * x0.x;
        ay += d0 * x0.y;
    }

    float dsv = g_dsq[v];
    float r = 2.0f / lam[0];
    float Lx = ax * dsv, Ly = ay * dsv;

    const float* base = g_Xt + (size_t)v * KK + lane * 2;
    float2 p1 = *(const float2*)(base + p1_off);
    float2 p2 = *(const float2*)(base + p2_off);
    float2 out;
    out.x = -2.0f * r * Lx + 2.0f * (r - 1.0f) * p1.x - p2.x;
    out.y = -2.0f * r * Ly + 2.0f * (r - 1.0f) * p1.y - p2.y;
    *(float2*)(g_Xt + (size_t)v * KK + out_off + lane * 2) = out;
}

// ---------------- 2-stage pipelined tf32 tensor-core GEMM + bias + ReLU ----------------
#define GBM 128
#define GBN 128
#define GBK 16
#define AROW 28
#define BROW 140
#define ASTG (GBM * AROW)          // 3584
#define STG  (ASTG + GBK * BROW)   // 5824 floats / stage

__device__ __forceinline__ void cp16(float* dstp, const float* src, int sz) {
    unsigned saddr = (unsigned)__cvta_generic_to_shared(dstp);
    asm volatile("cp.async.ca.shared.global [%0], [%1], 16, %2;"
                 :: "r"(saddr), "l"(src), "r"(sz));
}

__global__ __launch_bounds__(256)
void gemm_tf32(const float* __restrict__ W, const float* __restrict__ bias,
               float* __restrict__ C, int M) {
    __shared__ float sm[2 * STG];   // 46.6 KB

    int bx = blockIdx.x, by = blockIdx.y;
    int tid = threadIdx.x;
    int warp = tid >> 5, lane = tid & 31;
    int wm = warp >> 2;
    int wn = warp & 3;

    wmma::fragment<wmma::accumulator, 16, 16, 8, float> acc[4][2];
#pragma unroll
    for (int i = 0; i < 4; i++)
#pragma unroll
        for (int j = 0; j < 2; j++) wmma::fill_fragment(acc[i][j], 0.0f);

    const int NT = KK / GBK;   // 16

    auto load_stage = [&](int t, int stg) {
        float* s = sm + stg * STG;
        int k0 = t * GBK;
#pragma unroll
        for (int it = 0; it < 2; it++) {
            int idx = tid + it * 256;
            int row = idx >> 2, c4 = idx & 3;
            int gr = by * GBM + row;
            int grc = (gr < M) ? gr : (M - 1);
            const float* srcp = g_Xt + (size_t)grc * KK + k0 + c4 * 4;
            cp16(s + row * AROW + c4 * 4, srcp, (gr < M) ? 16 : 0);
        }
#pragma unroll
        for (int it = 0; it < 2; it++) {
            int idx = tid + it * 256;
            int row = idx >> 5, c4 = idx & 31;
            const float* srcp = W + (size_t)(k0 + row) * OF + bx * GBN + c4 * 4;
            cp16(s + ASTG + row * BROW + c4 * 4, srcp, 16);
        }
        asm volatile("cp.async.commit_group;");
    };

    load_stage(0, 0);

    for (int t = 0; t < NT; t++) {
        if (t + 1 < NT) {
            load_stage(t + 1, (t + 1) & 1);
            asm volatile("cp.async.wait_group 1;");
        } else {
            asm volatile("cp.async.wait_group 0;");
        }
        __syncthreads();

        const float* s = sm + (t & 1) * STG;
#pragma unroll
        for (int kk = 0; kk < GBK; kk += 8) {
            wmma::fragment<wmma::matrix_a, 16, 16, 8, wmma::precision::tf32, wmma::row_major> af[4];
            wmma::fragment<wmma::matrix_b, 16, 16, 8, wmma::precision::tf32, wmma::row_major> bf[2];
#pragma unroll
            for (int i = 0; i < 4; i++) {
                wmma::load_matrix_sync(af[i], s + (wm * 64 + i * 16) * AROW + kk, AROW);
#pragma unroll
                for (int e = 0; e < af[i].num_elements; e++)
                    af[i].x[e] = wmma::__float_to_tf32(af[i].x[e]);
            }
#pragma unroll
            for (int j = 0; j < 2; j++) {
                wmma::load_matrix_sync(bf[j], s + ASTG + kk * BROW + wn * 32 + j * 16, BROW);
#pragma unroll
                for (int e = 0; e < bf[j].num_elements; e++)
                    bf[j].x[e] = wmma::__float_to_tf32(bf[j].x[e]);
            }
#pragma unroll
            for (int i = 0; i < 4; i++)
#pragma unroll
                for (int j = 0; j < 2; j++)
                    wmma::mma_sync(acc[i][j], af[i], bf[j], acc[i][j]);
        }
        __syncthreads();
    }

    float* Cw = sm + warp * 256;
#pragma unroll
    for (int i = 0; i < 4; i++) {
#pragma unroll
        for (int j = 0; j < 2; j++) {
            wmma::store_matrix_sync(Cw, acc[i][j], 16, wmma::mem_row_major);
            __syncwarp();
            int r0 = by * GBM + wm * 64 + i * 16;
            int c0 = bx * GBN + wn * 32 + j * 16;
            int lr = lane >> 1;
            int lc = (lane & 1) * 8;
            int row = r0 + lr;
            if (row < M) {
#pragma unroll
                for (int c = 0; c < 8; c += 4) {
                    int col = c0 + lc + c;
                    float4 o;
                    o.x = fmaxf(Cw[lr * 16 + lc + c + 0] + bias[col + 0], 0.0f);
                    o.y = fmaxf(Cw[lr * 16 + lc + c + 1] + bias[col + 1], 0.0f);
                    o.z = fmaxf(Cw[lr * 16 + lc + c + 2] + bias[col + 2], 0.0f);
                    o.w = fmaxf(Cw[lr * 16 + lc + c + 3] + bias[col + 3], 0.0f);
                    *(float4*)(C + (size_t)row * OF + col) = o;
                }
            }
            __syncwarp();
        }
    }
}

// ---------------- launch ----------------
extern "C" void kernel_launch(void* const* d_in, const int* in_sizes, int n_in,
                              void* d_out, int out_size) {
    const float* signal = (const float*)d_in[0];
    const int*   src    = (const int*)d_in[1];
    const int*   dst    = (const int*)d_in[2];
    const float* lam    = (const float*)d_in[3];
    const float* W      = (const float*)d_in[4];
    const float* b      = (const float*)d_in[5];
    float* out = (float*)d_out;

    const int E = in_sizes[1];
    const int EB2 = ((E + 1) / 2 + 255) / 256;   // 2 edges per thread

    // degrees + CSR (g_deg arrives zeroed; scan3 re-zeroes it for the next call)
    deg_kernel<<<EB2, 256>>>(dst, E);
    scan1_kernel<<<SCAN_B, 1024>>>();
    scan3_kernel<<<SCAN_B, 1024>>>();
    fill_kernel<<<EB2, 256>>>(src, dst, E);

    // Chebyshev passes (warp per node; pass 1 fused with X0 init)
    const int CB = (NN * 32 + 255) / 256;
    cheb_step1_kernel<<<CB, 256>>>(lam, signal);
    cheb_step_kernel<<<CB, 256>>>(lam, /*in*/64,  /*out*/128, /*p1*/64,  /*p2*/0);
    cheb_step_kernel<<<CB, 256>>>(lam, /*in*/128, /*out*/192, /*p1*/128, /*p2*/64);

    // out = relu(Xt @ W + b)  -- 2-stage pipelined tf32 tensor cores
    dim3 grid(OF / GBN, (NN + GBM - 1) / GBM);
    gemm_tf32<<<grid, 256>>>(W, b, out, NN);
}

// round 16
// speedup vs baseline: 1.6721x; 1.5502x over previous
#include <cuda_runtime.h>
#include <cuda_fp16.h>
#include <mma.h>
using namespace nvcuda;

#define NN 50000
#define F  64        // in feats
#define KK 256       // F * K(=4) = GEMM K dim
#define OF 256       // out feats
#define EE 800000
#define SCAN_B 49    // ceil(NN/1024)

// ---- scratch (static __device__ arrays; no allocation allowed) ----
// g_deg relies on zero-init at module load; scan3 re-zeroes it after use.
__device__ int    g_deg[NN];
__device__ int    g_part[SCAN_B];
__device__ float  g_dsq[NN];
__device__ int    g_rowptr[NN + 1];
__device__ int    g_fill[NN];
__device__ int    g_col[EE];
__device__ float  g_Xt[(size_t)NN * KK];    // fp32 [X0|X1|X2|X3] (recurrence)
__device__ __half g_Xh[(size_t)NN * KK];    // fp16 mirror (GEMM A)
__device__ __half g_Wh[(size_t)KK * OF];    // fp16 W (GEMM B)

// ---------------- degree (2 edges/thread) ----------------
__global__ void deg_kernel(const int* __restrict__ dst, int E) {
    int t = blockIdx.x * blockDim.x + threadIdx.x;
    int e0 = t * 2;
    if (e0 + 1 < E) {
        int d0 = dst[e0];
        int d1 = dst[e0 + 1];
        atomicAdd(&g_deg[d0], 1);
        atomicAdd(&g_deg[d1], 1);
    } else if (e0 < E) {
        atomicAdd(&g_deg[dst[e0]], 1);
    }
}

// ---- 2-phase scan ----
__global__ __launch_bounds__(1024)
void scan1_kernel() {
    __shared__ int red[32];
    int i = blockIdx.x * 1024 + threadIdx.x;
    int d = (i < NN) ? g_deg[i] : 0;
    for (int o = 16; o > 0; o >>= 1) d += __shfl_down_sync(0xffffffff, d, o);
    if ((threadIdx.x & 31) == 0) red[threadIdx.x >> 5] = d;
    __syncthreads();
    if (threadIdx.x < 32) {
        int v = red[threadIdx.x];
        for (int o = 16; o > 0; o >>= 1) v += __shfl_down_sync(0xffffffff, v, o);
        if (threadIdx.x == 0) g_part[blockIdx.x] = v;
    }
}

__global__ __launch_bounds__(1024)
void scan3_kernel() {
    __shared__ int sh[1024];
    __shared__ int base_s;
    int t = threadIdx.x;
    int bid = blockIdx.x;
    int i = bid * 1024 + t;

    if (t == 0) {
        int s = 0;
        for (int k = 0; k < bid; k++) s += g_part[k];
        base_s = s;
        if (bid == SCAN_B - 1) {
            int tot = s;
            for (int k = bid; k < SCAN_B; k++) tot += g_part[k];
            g_rowptr[NN] = tot;
        }
    }

    int d = (i < NN) ? g_deg[i] : 0;
    sh[t] = d;
    __syncthreads();
    for (int off = 1; off < 1024; off <<= 1) {
        int u = (t >= off) ? sh[t - off] : 0;
        __syncthreads();
        sh[t] += u;
        __syncthreads();
    }
    if (i < NN) {
        g_rowptr[i] = base_s + sh[t] - d;
        g_fill[i] = 0;
        g_dsq[i] = rsqrtf(fmaxf((float)d, 1.0f));
        g_deg[i] = 0;
    }
}

// ---------------- CSR fill (2 edges/thread) ----------------
__global__ void fill_kernel(const int* __restrict__ src,
                            const int* __restrict__ dst, int E) {
    int t = blockIdx.x * blockDim.x + threadIdx.x;
    int e0 = t * 2;
    if (e0 + 1 < E) {
        int d0 = dst[e0];
        int d1 = dst[e0 + 1];
        int s0 = src[e0];
        int s1 = src[e0 + 1];
        int p0 = g_rowptr[d0] + atomicAdd(&g_fill[d0], 1);
        int p1 = g_rowptr[d1] + atomicAdd(&g_fill[d1], 1);
        g_col[p0] = s0;
        g_col[p1] = s1;
    } else if (e0 < E) {
        int d0 = dst[e0];
        int p0 = g_rowptr[d0] + atomicAdd(&g_fill[d0], 1);
        g_col[p0] = src[e0];
    }
}

// ---------------- W -> fp16 (once per launch) ----------------
__global__ void wconv_kernel(const float* __restrict__ W) {
    int i = blockIdx.x * blockDim.x + threadIdx.x;   // half2 index
    if (i >= KK * OF / 2) return;
    float2 w = ((const float2*)W)[i];
    ((__half2*)g_Wh)[i] = __floats2half2_rn(w.x, w.y);
}

// ---------------- cheb pass 1 (fused init): reads signal only ----------------
__global__ __launch_bounds__(256)
void cheb_step1_kernel(const float* __restrict__ lam,
                       const float* __restrict__ sig) {
    int gtid = blockIdx.x * blockDim.x + threadIdx.x;
    int v = gtid >> 5;
    int lane = gtid & 31;
    if (v >= NN) return;

    int p   = g_rowptr[v];
    int end = g_rowptr[v + 1];
    float ax = 0.0f, ay = 0.0f;

    const float* Sin = sig + lane * 2;
    for (; p + 3 < end; p += 4) {
        int s0 = g_col[p];
        int s1 = g_col[p + 1];
        int s2 = g_col[p + 2];
        int s3 = g_col[p + 3];
        float d0 = g_dsq[s0];
        float d1 = g_dsq[s1];
        float d2 = g_dsq[s2];
        float d3 = g_dsq[s3];
        float2 x0 = *(const float2*)(Sin + (size_t)s0 * F);
        float2 x1 = *(const float2*)(Sin + (size_t)s1 * F);
        float2 x2 = *(const float2*)(Sin + (size_t)s2 * F);
        float2 x3 = *(const float2*)(Sin + (size_t)s3 * F);
        ax += d0 * x0.x + d1 * x1.x + d2 * x2.x + d3 * x3.x;
        ay += d0 * x0.y + d1 * x1.y + d2 * x2.y + d3 * x3.y;
    }
    for (; p < end; p++) {
        int s0 = g_col[p];
        float d0 = g_dsq[s0];
        float2 x0 = *(const float2*)(Sin + (size_t)s0 * F);
        ax += d0 * x0.x;
        ay += d0 * x0.y;
    }

    float dsv = g_dsq[v];
    float r = 2.0f / lam[0];
    float Lx = ax * dsv, Ly = ay * dsv;

    float2 x0v = *(const float2*)(sig + (size_t)v * F + lane * 2);
    float2 out;
    out.x = -r * Lx + (r - 1.0f) * x0v.x;
    out.y = -r * Ly + (r - 1.0f) * x0v.y;

    float* row = g_Xt + (size_t)v * KK + lane * 2;
    *(float2*)(row) = x0v;            // X0 (fp32)
    *(float2*)(row + 64) = out;       // X1 (fp32)
    __half2* rowh = (__half2*)(g_Xh + (size_t)v * KK + lane * 2);
    rowh[0]  = __floats2half2_rn(x0v.x, x0v.y);   // X0 (fp16)
    rowh[32] = __floats2half2_rn(out.x, out.y);   // X1 (fp16, +64 halves)
}

// ---------------- cheb passes 2..3 (fp32 recurrence + fp16 mirror write) ----------------
__global__ __launch_bounds__(256)
void cheb_step_kernel(const float* __restrict__ lam,
                      int in_off, int out_off, int p1_off, int p2_off) {
    int gtid = blockIdx.x * blockDim.x + threadIdx.x;
    int v = gtid >> 5;
    int lane = gtid & 31;
    if (v >= NN) return;

    int p   = g_rowptr[v];
    int end = g_rowptr[v + 1];
    float ax = 0.0f, ay = 0.0f;

    const float* Xin = g_Xt + in_off + lane * 2;
    for (; p + 3 < end; p += 4) {
        int s0 = g_col[p];
        int s1 = g_col[p + 1];
        int s2 = g_col[p + 2];
        int s3 = g_col[p + 3];
        float d0 = g_dsq[s0];
        float d1 = g_dsq[s1];
        float d2 = g_dsq[s2];
        float d3 = g_dsq[s3];
        float2 x0 = *(const float2*)(Xin + (size_t)s0 * KK);
        float2 x1 = *(const float2*)(Xin + (size_t)s1 * KK);
        float2 x2 = *(const float2*)(Xin + (size_t)s2 * KK);
        float2 x3 = *(const float2*)(Xin + (size_t)s3 * KK);
        ax += d0 * x0.x + d1 * x1.x + d2 * x2.x + d3 * x3.x;
        ay += d0 * x0.y + d1 * x1.y + d2 * x2.y + d3 * x3.y;
    }
    for (; p < end; p++) {
        int s0 = g_col[p];
        float d0 = g_dsq[s0];
        float2 x0 = *(const float2*)(Xin + (size_t)s0 * KK);
        ax += d0 * x0.x;
        ay += d0 * x0.y;
    }

    float dsv = g_dsq[v];
    float r = 2.0f / lam[0];
    float Lx = ax * dsv, Ly = ay * dsv;

    const float* base = g_Xt + (size_t)v * KK + lane * 2;
    float2 p1 = *(const float2*)(base + p1_off);
    float2 p2 = *(const float2*)(base + p2_off);
    float2 out;
    out.x = -2.0f * r * Lx + 2.0f * (r - 1.0f) * p1.x - p2.x;
    out.y = -2.0f * r * Ly + 2.0f * (r - 1.0f) * p1.y - p2.y;
    *(float2*)(g_Xt + (size_t)v * KK + out_off + lane * 2) = out;
    *(__half2*)(g_Xh + (size_t)v * KK + out_off + lane * 2) =
        __floats2half2_rn(out.x, out.y);
}

// ---------------- 2-stage pipelined fp16 tensor-core GEMM + bias + ReLU ----------------
// C[M, OF] = relu(Xh[M, KK] @ Wh[KK, OF] + b), fp32 accum
#define GBM 128
#define GBN 128
#define GBKH 32
#define AROWH 40                     // halves per A row (32 + 8)
#define BROWH 136                    // halves per B row (128 + 8)
#define ASTGH (GBM * AROWH)          // 5120 halves
#define STGH  (ASTGH + GBKH * BROWH) // 5120 + 4352 = 9472 halves / stage

__device__ __forceinline__ void cp16h(__half* dstp, const __half* src, int sz) {
    unsigned saddr = (unsigned)__cvta_generic_to_shared(dstp);
    asm volatile("cp.async.ca.shared.global [%0], [%1], 16, %2;"
                 :: "r"(saddr), "l"(src), "r"(sz));
}

__global__ __launch_bounds__(256)
void gemm_fp16(const float* __restrict__ bias, float* __restrict__ C, int M) {
    __shared__ __half sm[2 * STGH];   // 37.9 KB

    int bx = blockIdx.x, by = blockIdx.y;
    int tid = threadIdx.x;
    int warp = tid >> 5, lane = tid & 31;
    int wm = warp >> 2;   // 0..1 : 64-row slab
    int wn = warp & 3;    // 0..3 : 32-col slab

    wmma::fragment<wmma::accumulator, 16, 16, 16, float> acc[4][2];
#pragma unroll
    for (int i = 0; i < 4; i++)
#pragma unroll
        for (int j = 0; j < 2; j++) wmma::fill_fragment(acc[i][j], 0.0f);

    const int NT = KK / GBKH;   // 8 tiles

    auto load_stage = [&](int t, int stg) {
        __half* s = sm + stg * STGH;
        int k0 = t * GBKH;
        // A: 128 rows x 32 halves = 512 x 8-half chunks (2 per thread)
#pragma unroll
        for (int it = 0; it < 2; it++) {
            int idx = tid + it * 256;
            int row = idx >> 2, c8 = idx & 3;
            int gr = by * GBM + row;
            int grc = (gr < M) ? gr : (M - 1);
            const __half* srcp = g_Xh + (size_t)grc * KK + k0 + c8 * 8;
            cp16h(s + row * AROWH + c8 * 8, srcp, (gr < M) ? 16 : 0);
        }
        // B: 32 rows x 128 halves = 512 x 8-half chunks (2 per thread)
#pragma unroll
        for (int it = 0; it < 2; it++) {
            int idx = tid + it * 256;
            int row = idx >> 4, c8 = idx & 15;
            const __half* srcp = g_Wh + (size_t)(k0 + row) * OF + bx * GBN + c8 * 8;
            cp16h(s + ASTGH + row * BROWH + c8 * 8, srcp, 16);
        }
        asm volatile("cp.async.commit_group;");
    };

    load_stage(0, 0);

    for (int t = 0; t < NT; t++) {
        if (t + 1 < NT) {
            load_stage(t + 1, (t + 1) & 1);
            asm volatile("cp.async.wait_group 1;");
        } else {
            asm volatile("cp.async.wait_group 0;");
        }
        __syncthreads();

        const __half* s = sm + (t & 1) * STGH;
#pragma unroll
        for (int kk = 0; kk < GBKH; kk += 16) {
            wmma::fragment<wmma::matrix_a, 16, 16, 16, __half, wmma::row_major> af[4];
            wmma::fragment<wmma::matrix_b, 16, 16, 16, __half, wmma::row_major> bf[2];
#pragma unroll
            for (int i = 0; i < 4; i++)
                wmma::load_matrix_sync(af[i], s + (wm * 64 + i * 16) * AROWH + kk, AROWH);
#pragma unroll
            for (int j = 0; j < 2; j++)
                wmma::load_matrix_sync(bf[j], s + ASTGH + kk * BROWH + wn * 32 + j * 16, BROWH);
#pragma unroll
            for (int i = 0; i < 4; i++)
#pragma unroll
                for (int j = 0; j < 2; j++)
                    wmma::mma_sync(acc[i][j], af[i], bf[j], acc[i][j]);
        }
        __syncthreads();
    }

    // epilogue: stage fp32 fragments through smem, add bias + relu
    float* Cw = (float*)sm + warp * 256;
#pragma unroll
    for (int i = 0; i < 4; i++) {
#pragma unroll
        for (int j = 0; j < 2; j++) {
            wmma::store_matrix_sync(Cw, acc[i][j], 16, wmma::mem_row_major);
            __syncwarp();
            int r0 = by * GBM + wm * 64 + i * 16;
            int c0 = bx * GBN + wn * 32 + j * 16;
            int lr = lane >> 1;
            int lc = (lane & 1) * 8;
            int row = r0 + lr;
            if (row < M) {
#pragma unroll
                for (int c = 0; c < 8; c += 4) {
                    int col = c0 + lc + c;
                    float4 o;
                    o.x = fmaxf(Cw[lr * 16 + lc + c + 0] + bias[col + 0], 0.0f);
                    o.y = fmaxf(Cw[lr * 16 + lc + c + 1] + bias[col + 1], 0.0f);
                    o.z = fmaxf(Cw[lr * 16 + lc + c + 2] + bias[col + 2], 0.0f);
                    o.w = fmaxf(Cw[lr * 16 + lc + c + 3] + bias[col + 3], 0.0f);
                    *(float4*)(C + (size_t)row * OF + col) = o;
                }
            }
            __syncwarp();
        }
    }
}

// ---------------- launch ----------------
extern "C" void kernel_launch(void* const* d_in, const int* in_sizes, int n_in,
                              void* d_out, int out_size) {
    const float* signal = (const float*)d_in[0];
    const int*   src    = (const int*)d_in[1];
    const int*   dst    = (const int*)d_in[2];
    const float* lam    = (const float*)d_in[3];
    const float* W      = (const float*)d_in[4];
    const float* b      = (const float*)d_in[5];
    float* out = (float*)d_out;

    const int E = in_sizes[1];
    const int EB2 = ((E + 1) / 2 + 255) / 256;   // 2 edges per thread

    // degrees + CSR
    deg_kernel<<<EB2, 256>>>(dst, E);
    scan1_kernel<<<SCAN_B, 1024>>>();
    scan3_kernel<<<SCAN_B, 1024>>>();
    fill_kernel<<<EB2, 256>>>(src, dst, E);

    // W -> fp16 (independent; overlaps preproc in the graph's stream order)
    wconv_kernel<<<(KK * OF / 2 + 255) / 256, 256>>>(W);

    // Chebyshev passes (warp per node; pass 1 fused with X0 init; dual fp32+fp16 writes)
    const int CB = (NN * 32 + 255) / 256;
    cheb_step1_kernel<<<CB, 256>>>(lam, signal);
    cheb_step_kernel<<<CB, 256>>>(lam, /*in*/64,  /*out*/128, /*p1*/64,  /*p2*/0);
    cheb_step_kernel<<<CB, 256>>>(lam, /*in*/128, /*out*/192, /*p1*/128, /*p2*/64);

    // out = relu(Xh @ Wh + b)  -- 2-stage pipelined fp16 tensor cores, fp32 accum
    dim3 grid(OF / GBN, (NN + GBM - 1) / GBM);
    gemm_fp16<<<grid, 256>>>(b, out, NN);
}